// round 12
// baseline (speedup 1.0000x reference)
#include <cuda_runtime.h>
#include <cuda_bf16.h>

// ModernBertCanonLayer: varlen depthwise conv (K=5) + bias + residual.
// Round-11: software-pipelined register stream. Load-to-use distance = one
// full unroll-4 iteration (13-float4 rolling state), so each warp's loads
// stay outstanding while it computes the previous group -> no convoy stalls.
// 192-thread CTAs, 3 CTAs/SM, grid = 888 = exactly 2 waves.

#define CCH   768
#define C4    (CCH / 4)      // 192 float4 per row
#define GRID  888            // 2 exact waves of 444 resident CTAs (3/SM)
#define NSTREAMS GRID        // one token stream per CTA

#define FMA4(acc, wk, r)                                   \
    acc.x = fmaf((wk)[0], (r).x, acc.x);                   \
    acc.y = fmaf((wk)[1], (r).y, acc.y);                   \
    acc.z = fmaf((wk)[2], (r).z, acc.z);                   \
    acc.w = fmaf((wk)[3], (r).w, acc.w);

#define FMA4M(acc, wk, r, m)                               \
    acc.x = fmaf((m) ? (wk)[0] : 0.f, (r).x, acc.x);       \
    acc.y = fmaf((m) ? (wk)[1] : 0.f, (r).y, acc.y);       \
    acc.z = fmaf((m) ? (wk)[2] : 0.f, (r).z, acc.z);       \
    acc.w = fmaf((m) ? (wk)[3] : 0.f, (r).w, acc.w);

// Fast token (all taps in-segment): rows A0..A4, center A2.
#define TOKEN_FAST(po, A0, A1, A2, A3, A4)                 \
    do {                                                   \
        float4 acc = b4;                                   \
        FMA4(acc, w[0], A0); FMA4(acc, w[1], A1);          \
        FMA4(acc, w[2], A2); FMA4(acc, w[3], A3);          \
        FMA4(acc, w[4], A4);                               \
        float4 o;                                          \
        o.x = (A2).x + acc.x; o.y = (A2).y + acc.y;        \
        o.z = (A2).z + acc.z; o.w = (A2).w + acc.w;        \
        __stcs((po), o);                                   \
    } while (0)

// Slow token: advances segment window and applies per-tap masks.
// Clamped/garbage halo rows are always masked out here.
#define TOKEN_SLOW(it, po, A0, A1, A2, A3, A4)             \
    do {                                                   \
        while ((it) >= hhi) { ++ss; llo = s_cu[ss]; hhi = s_cu[ss + 1]; } \
        float4 acc = b4;                                   \
        FMA4M(acc, w[0], A0, (it) - 2 >= llo);             \
        FMA4M(acc, w[1], A1, (it) - 1 >= llo);             \
        FMA4(acc, w[2], A2);                               \
        FMA4M(acc, w[3], A3, (it) + 1 < hhi);              \
        FMA4M(acc, w[4], A4, (it) + 2 < hhi);              \
        float4 o;                                          \
        o.x = (A2).x + acc.x; o.y = (A2).y + acc.y;        \
        o.z = (A2).z + acc.z; o.w = (A2).w + acc.w;        \
        __stcs((po), o);                                   \
    } while (0)

__global__ __launch_bounds__(C4, 3)
void canon_kernel(const float* __restrict__ x,
                  const int*   __restrict__ cu, int ncu,
                  const float* __restrict__ weight,
                  const float* __restrict__ bias,
                  float*       __restrict__ out,
                  int T)
{
    __shared__ int s_cu[64];
    if (threadIdx.x < ncu) s_cu[threadIdx.x] = cu[threadIdx.x];
    __syncthreads();

    const int c4 = threadIdx.x;                              // 0..191
    const int S  = blockIdx.x;                               // stream id

    // Balanced split across streams (len differs by at most 1 token).
    const int Lsmall = T / NSTREAMS;
    const int R      = T - Lsmall * NSTREAMS;
    const int len    = Lsmall + (S < R ? 1 : 0);
    const int base   = S * Lsmall + (S < R ? S : R);
    if (len <= 0) return;

    float w[5][4];
    {
        const int c0 = c4 * 4;
        #pragma unroll
        for (int j = 0; j < 4; ++j)
            #pragma unroll
            for (int k = 0; k < 5; ++k)
                w[k][j] = weight[(c0 + j) * 5 + k];
    }
    const float4 b4 = reinterpret_cast<const float4*>(bias)[c4];

    const float4* __restrict__ x4 = reinterpret_cast<const float4*>(x);
    float4* __restrict__       o4 = reinterpret_cast<float4*>(out);

    // Segment of token `base` (searchsorted-right; handles empty sequences).
    int s = 0;
    while (base >= s_cu[s + 1]) ++s;
    int lo = s_cu[s], hi = s_cu[s + 1];

    const int tmax = T - 1;
    const float4* plim = x4 + (size_t)tmax * C4 + c4;        // last valid row ptr

    // Prologue: rows base-2 .. base+6 (clamped; masks neutralize garbage).
    float4 r0, r1, r2, r3, r4;                               // rows i-2 .. i+2
    float4 a0, a1, a2, a3;                                   // rows i+3 .. i+6 (arrived)
    {
        int j0 = base - 2 > 0 ? base - 2 : 0;
        int j1 = base - 1 > 0 ? base - 1 : 0;
        r0 = x4[(size_t)j0   * C4 + c4];
        r1 = x4[(size_t)j1   * C4 + c4];
        r2 = x4[(size_t)base * C4 + c4];
        const float4* p;
        p = x4 + (size_t)(base + 1) * C4 + c4; r3 = *(p <= plim ? p : plim);
        p = x4 + (size_t)(base + 2) * C4 + c4; r4 = *(p <= plim ? p : plim);
        p = x4 + (size_t)(base + 3) * C4 + c4; a0 = *(p <= plim ? p : plim);
        p = x4 + (size_t)(base + 4) * C4 + c4; a1 = *(p <= plim ? p : plim);
        p = x4 + (size_t)(base + 5) * C4 + c4; a2 = *(p <= plim ? p : plim);
        p = x4 + (size_t)(base + 6) * C4 + c4; a3 = *(p <= plim ? p : plim);
    }

    const int iend = base + len;
    int i = base;

    // Walking pointers: px -> row i+7 (next prefetch), po -> row i (output).
    const float4* px = x4 + (size_t)(i + 7) * C4 + c4;
    float4*       po = o4 + (size_t)i * C4 + c4;

    // ---- pipelined unroll-4 loop: loads for NEXT iteration issued first ----
    for (; i + 3 < iend; i += 4) {
        // Issue rows i+7 .. i+10 (consumed only next iteration -> stays
        // outstanding for a full group of compute).
        float4 n0 = *(px          <= plim ? px          : plim);
        float4 n1 = *(px + C4     <= plim ? px + C4     : plim);
        float4 n2 = *(px + 2 * C4 <= plim ? px + 2 * C4 : plim);
        float4 n3 = *(px + 3 * C4 <= plim ? px + 3 * C4 : plim);

        // Catch segment window up to token i (warp-uniform).
        while (i >= hi) { ++s; lo = s_cu[s]; hi = s_cu[s + 1]; }

        if (i - 2 >= lo && i + 5 < hi) {
            TOKEN_FAST(po         , r0, r1, r2, r3, r4);
            TOKEN_FAST(po + C4    , r1, r2, r3, r4, a0);
            TOKEN_FAST(po + 2 * C4, r2, r3, r4, a0, a1);
            TOKEN_FAST(po + 3 * C4, r3, r4, a0, a1, a2);
        } else {
            int ss = s, llo = lo, hhi = hi;
            TOKEN_SLOW(i    , po         , r0, r1, r2, r3, r4);
            TOKEN_SLOW(i + 1, po + C4    , r1, r2, r3, r4, a0);
            TOKEN_SLOW(i + 2, po + 2 * C4, r2, r3, r4, a0, a1);
            TOKEN_SLOW(i + 3, po + 3 * C4, r3, r4, a0, a1, a2);
        }

        // Shift: new window = rows i+2..i+6, new arrived buf = rows i+7..i+10.
        r0 = r4; r1 = a0; r2 = a1; r3 = a2; r4 = a3;
        a0 = n0; a1 = n1; a2 = n2; a3 = n3;
        px += 4 * C4;
        po += 4 * C4;
    }

    // ---- scalar tail (<= 3 tokens): rows already arrived in a0..a2 ----
    for (; i < iend; ++i) {
        while (i >= hi) { ++s; lo = s_cu[s]; hi = s_cu[s + 1]; }
        int ss = s, llo = lo, hhi = hi;
        TOKEN_SLOW(i, po, r0, r1, r2, r3, r4);
        r0 = r1; r1 = r2; r2 = r3; r3 = r4; r4 = a0;
        a0 = a1; a1 = a2; a2 = a3;
        po += C4;
    }
}

extern "C" void kernel_launch(void* const* d_in, const int* in_sizes, int n_in,
                              void* d_out, int out_size)
{
    const float* x      = (const float*)d_in[0];
    const int*   cu     = (const int*)  d_in[1];
    const float* weight = (const float*)d_in[2];
    const float* bias   = (const float*)d_in[3];
    float*       out    = (float*)d_out;

    const int T   = in_sizes[0] / CCH;
    const int ncu = in_sizes[1];

    canon_kernel<<<GRID, C4>>>(x, cu, ncu, weight, bias, out, T);
}